// round 17
// baseline (speedup 1.0000x reference)
#include <cuda_runtime.h>
#include <cuda_bf16.h>
#include <cstdint>
#include <math.h>

#define L_  8
#define D_  1024
#define H_  16
#define DH_ 64
#define DI_ 4096
#define V_  32000
#define B_  2
#define S_  1024
#define T_  (B_*S_)

typedef __nv_bfloat16 bf16;

// ---------------- fp32 scratch ----------------
__device__ float g_h   [T_*D_];
__device__ float g_cos [S_*32];
__device__ float g_sin [S_*32];
__device__ float g_bqkv[L_*3*D_];

// ---------------- split bf16 scratch (hi/lo) ----------------
__device__ bf16 s_wqkv_h[L_*3*D_*D_], s_wqkv_l[L_*3*D_*D_];
__device__ bf16 s_wo_h[L_*D_*D_],   s_wo_l[L_*D_*D_];
__device__ bf16 s_wgu_h[(size_t)L_*2*DI_*D_], s_wgu_l[(size_t)L_*2*DI_*D_];
__device__ bf16 s_wd_h[L_*D_*DI_],  s_wd_l[L_*D_*DI_];
__device__ bf16 s_emb_h[V_*D_],     s_emb_l[V_*D_];
__device__ bf16 s_hn_h[T_*D_],      s_hn_l[T_*D_];
__device__ bf16 s_q_h [T_*D_],      s_q_l [T_*D_];
__device__ bf16 s_k_h [T_*D_],      s_k_l [T_*D_];
__device__ bf16 s_vt_h[T_*D_],      s_vt_l[T_*D_];
__device__ bf16 s_y_h [T_*D_],      s_y_l [T_*D_];
__device__ bf16 s_ga_h[T_*DI_],     s_ga_l[T_*DI_];

// ---------------- helpers ----------------
__device__ __forceinline__ void split1(float v, bf16& h, bf16& l) {
    h = __float2bfloat16(v);
    l = __float2bfloat16(v - __bfloat162float(h));
}

__device__ __forceinline__ void split_store2(bf16* H, bf16* Lo, size_t off, float v0, float v1) {
    bf16 h0, l0, h1, l1;
    split1(v0, h0, l0);
    split1(v1, h1, l1);
    __nv_bfloat162 th; th.x = h0; th.y = h1;
    __nv_bfloat162 tl; tl.x = l0; tl.y = l1;
    *(__nv_bfloat162*)(H  + off) = th;
    *(__nv_bfloat162*)(Lo + off) = tl;
}

__device__ __forceinline__ void splitpack2(float a, float b, uint32_t& h, uint32_t& l) {
    bf16 ha, la, hb, lb;
    split1(a, ha, la);
    split1(b, hb, lb);
    h = ((uint32_t)__bfloat16_as_ushort(hb) << 16) | __bfloat16_as_ushort(ha);
    l = ((uint32_t)__bfloat16_as_ushort(lb) << 16) | __bfloat16_as_ushort(la);
}

__global__ void split_kernel(const float* __restrict__ x, bf16* __restrict__ h,
                             bf16* __restrict__ l, int n4) {
    int i = blockIdx.x * blockDim.x + threadIdx.x;
    if (i >= n4) return;
    float4 v = ((const float4*)x)[i];
    bf16 h0,l0,h1,l1,h2,l2,h3,l3;
    split1(v.x, h0, l0); split1(v.y, h1, l1);
    split1(v.z, h2, l2); split1(v.w, h3, l3);
    ((ushort4*)h)[i] = make_ushort4(__bfloat16_as_ushort(h0), __bfloat16_as_ushort(h1),
                                    __bfloat16_as_ushort(h2), __bfloat16_as_ushort(h3));
    ((ushort4*)l)[i] = make_ushort4(__bfloat16_as_ushort(l0), __bfloat16_as_ushort(l1),
                                    __bfloat16_as_ushort(l2), __bfloat16_as_ushort(l3));
}

__global__ void split_pack_kernel(const float* __restrict__ x, bf16* __restrict__ h,
                                  bf16* __restrict__ l, int row_off) {
    int i = blockIdx.x * blockDim.x + threadIdx.x;
    if (i >= L_*D_*D_/4) return;
    int lay = i / (D_*D_/4);
    int rem = i % (D_*D_/4);
    int r   = rem / (D_/4);
    int c4  = rem % (D_/4);
    float4 v = ((const float4*)x)[i];
    int d4 = lay*(3*D_*D_/4) + (row_off + r)*(D_/4) + c4;
    bf16 h0,l0,h1,l1,h2,l2,h3,l3;
    split1(v.x, h0, l0); split1(v.y, h1, l1);
    split1(v.z, h2, l2); split1(v.w, h3, l3);
    ((ushort4*)h)[d4] = make_ushort4(__bfloat16_as_ushort(h0), __bfloat16_as_ushort(h1),
                                     __bfloat16_as_ushort(h2), __bfloat16_as_ushort(h3));
    ((ushort4*)l)[d4] = make_ushort4(__bfloat16_as_ushort(l0), __bfloat16_as_ushort(l1),
                                     __bfloat16_as_ushort(l2), __bfloat16_as_ushort(l3));
}

__global__ void split_pack_gu_kernel(const float* __restrict__ wg, const float* __restrict__ wu,
                                     bf16* __restrict__ h, bf16* __restrict__ l) {
    int i = blockIdx.x * blockDim.x + threadIdx.x;
    if (i >= L_*DI_*D_/4) return;
    int lay = i / (DI_*D_/4);
    int rem = i % (DI_*D_/4);
    int r   = rem / (D_/4);
    int c4  = rem % (D_/4);
    float4 vg = ((const float4*)wg)[i];
    float4 vu = ((const float4*)wu)[i];
    size_t base = (size_t)lay*(2*DI_*D_/4);
    size_t dg = base + (size_t)(2*r)  *(D_/4) + c4;
    size_t du = base + (size_t)(2*r+1)*(D_/4) + c4;
    bf16 h0,l0,h1,l1,h2,l2,h3,l3;
    split1(vg.x, h0, l0); split1(vg.y, h1, l1);
    split1(vg.z, h2, l2); split1(vg.w, h3, l3);
    ((ushort4*)h)[dg] = make_ushort4(__bfloat16_as_ushort(h0), __bfloat16_as_ushort(h1),
                                     __bfloat16_as_ushort(h2), __bfloat16_as_ushort(h3));
    ((ushort4*)l)[dg] = make_ushort4(__bfloat16_as_ushort(l0), __bfloat16_as_ushort(l1),
                                     __bfloat16_as_ushort(l2), __bfloat16_as_ushort(l3));
    split1(vu.x, h0, l0); split1(vu.y, h1, l1);
    split1(vu.z, h2, l2); split1(vu.w, h3, l3);
    ((ushort4*)h)[du] = make_ushort4(__bfloat16_as_ushort(h0), __bfloat16_as_ushort(h1),
                                     __bfloat16_as_ushort(h2), __bfloat16_as_ushort(h3));
    ((ushort4*)l)[du] = make_ushort4(__bfloat16_as_ushort(l0), __bfloat16_as_ushort(l1),
                                     __bfloat16_as_ushort(l2), __bfloat16_as_ushort(l3));
}

__global__ void pack_bias_kernel(const float* __restrict__ bq, const float* __restrict__ bk,
                                 const float* __restrict__ bv, float* __restrict__ dst) {
    int i = blockIdx.x * blockDim.x + threadIdx.x;
    if (i >= L_*3*D_) return;
    int lay = i / (3*D_);
    int j   = i % (3*D_);
    float v = (j < D_) ? bq[lay*D_ + j]
            : (j < 2*D_) ? bk[lay*D_ + j - D_]
            : bv[lay*D_ + j - 2*D_];
    dst[i] = v;
}

// ---------------- small kernels ----------------
__global__ void embed_kernel(const int* __restrict__ x, const float* __restrict__ emb,
                             float* __restrict__ h) {
    int i = blockIdx.x * blockDim.x + threadIdx.x;
    int t = i / (D_/4);
    int c = i % (D_/4);
    float4 v = *(const float4*)(emb + (size_t)x[t]*D_ + c*4);
    *(float4*)(h + (size_t)t*D_ + c*4) = v;
}

__global__ void rope_cache_kernel() {
    int i = blockIdx.x * blockDim.x + threadIdx.x;
    if (i >= S_*32) return;
    int s = i / 32, j = i % 32;
    double inv = pow(10000.0, -(double)j / 32.0);
    double ph = (double)s * inv;
    g_cos[i] = (float)cos(ph);
    g_sin[i] = (float)sin(ph);
}

__global__ void rmsnorm_kernel(const float* __restrict__ x, const float* __restrict__ w,
                               bf16* __restrict__ oh, bf16* __restrict__ ol) {
    int t = blockIdx.x;
    int tid = threadIdx.x;
    const float* xp = x + (size_t)t*D_;
    float v[4];
    float s = 0.f;
    #pragma unroll
    for (int i = 0; i < 4; i++) { v[i] = xp[tid + i*256]; s += v[i]*v[i]; }
    #pragma unroll
    for (int off = 16; off; off >>= 1) s += __shfl_xor_sync(0xffffffffu, s, off);
    __shared__ float red[8];
    if ((tid & 31) == 0) red[tid >> 5] = s;
    __syncthreads();
    if (tid < 32) {
        float s2 = (tid < 8) ? red[tid] : 0.f;
        #pragma unroll
        for (int off = 4; off; off >>= 1) s2 += __shfl_xor_sync(0xffffffffu, s2, off);
        if (tid == 0) red[0] = s2;
    }
    __syncthreads();
    float r = rsqrtf(red[0] * (1.f/(float)D_) + 1e-6f);
    size_t base = (size_t)t*D_;
    #pragma unroll
    for (int i = 0; i < 4; i++) {
        int idx = tid + i*256;
        split1(w[idx] * v[i] * r, oh[base+idx], ol[base+idx]);
    }
}

// ---------------- bf16x3 GEMM on pre-split operands ----------------
enum { EPI_NONE = 0, EPI_BIAS_RES_AT = 2, EPI_RES_AT = 3,
       EPI_QKV = 8, EPI_SWIGLU = 9 };

__device__ __forceinline__ void mma_bf16(float* d, const uint32_t* a, const uint32_t* b) {
    asm volatile(
        "mma.sync.aligned.m16n8k16.row.col.f32.bf16.bf16.f32 "
        "{%0,%1,%2,%3}, {%4,%5,%6,%7}, {%8,%9}, {%0,%1,%2,%3};\n"
        : "+f"(d[0]), "+f"(d[1]), "+f"(d[2]), "+f"(d[3])
        : "r"(a[0]), "r"(a[1]), "r"(a[2]), "r"(a[3]),
          "r"(b[0]), "r"(b[1]));
}

#define CP_ASYNC16(dst, src) \
    asm volatile("cp.async.cg.shared.global [%0], [%1], 16;" :: "r"(dst), "l"(src))
#define CP_COMMIT() asm volatile("cp.async.commit_group;" ::: "memory")
#define CP_WAIT0()  asm volatile("cp.async.wait_group 0;"  ::: "memory")

// SPLITK: blockIdx.z indexes a K-range of size K/SPLITK; atomic epilogues accumulate.
template<int BM, int BN, int BK, int WM, int WN, int EPI, int MINB, int SPLITK>
__global__ __launch_bounds__((BM/WM)*(BN/WN)*32, MINB)
void gemm_tc(const bf16* __restrict__ Agh, const bf16* __restrict__ Agl,
             const bf16* __restrict__ Bgh, const bf16* __restrict__ Bgl,
             float* __restrict__ C, bf16* __restrict__ Oh, bf16* __restrict__ Ol,
             const float* __restrict__ bias,
             int M, int N, int K, int lda, int ldb, int ldc)
{
    constexpr int WARPS_N = BN/WN;
    constexpr int THREADS = (BM/WM)*(BN/WN)*32;
    constexpr int MT = WM/16;
    constexpr int NT = WN/8;
    constexpr int SP = BK/2 + 4;
    constexpr int SZA = BM*SP;
    constexpr int SZB = BN*SP;
    constexpr int STAGE = 2*SZA + 2*SZB;
    constexpr int NCA = (BM*BK/8)/THREADS;
    constexpr int NCB = (BN*BK/8)/THREADS;

    extern __shared__ uint32_t smem_u[];

    const int tid = threadIdx.x;
    const int m0 = blockIdx.y * BM;
    const int n0 = blockIdx.x * BN;
    const int KS   = K / SPLITK;
    const int Kofs = blockIdx.z * KS;

    const int warp = tid >> 5;
    const int lane = tid & 31;
    const int g = lane >> 2;
    const int c = lane & 3;
    const int wn = warp % WARPS_N;
    const int wm = warp / WARPS_N;

    float acc[MT][NT][4];
    #pragma unroll
    for (int i = 0; i < MT; i++)
        #pragma unroll
        for (int j = 0; j < NT; j++)
            #pragma unroll
            for (int r = 0; r < 4; r++) acc[i][j][r] = 0.f;

    const int nk = KS / BK;

    const uint32_t smb = (uint32_t)__cvta_generic_to_shared(smem_u);
    auto cp_tile = [&](int kt, int s) {
        const uint32_t Ah = smb + s*STAGE*4;
        const uint32_t Al = Ah + SZA*4;
        const uint32_t Bh = Al + SZA*4;
        const uint32_t Bl = Bh + SZB*4;
        #pragma unroll
        for (int i = 0; i < NCA; i++) {
            int f  = tid + i*THREADS;
            int r  = f / (BK/8);
            int c8 = f % (BK/8);
            size_t   go = (size_t)(m0+r)*lda + Kofs + kt + c8*8;
            uint32_t so = (uint32_t)(r*SP + c8*4)*4;
            CP_ASYNC16(Ah + so, Agh + go);
            CP_ASYNC16(Al + so, Agl + go);
        }
        #pragma unroll
        for (int i = 0; i < NCB; i++) {
            int f  = tid + i*THREADS;
            int r  = f / (BK/8);
            int c8 = f % (BK/8);
            size_t   go = (size_t)(n0+r)*ldb + Kofs + kt + c8*8;
            uint32_t so = (uint32_t)(r*SP + c8*4)*4;
            CP_ASYNC16(Bh + so, Bgh + go);
            CP_ASYNC16(Bl + so, Bgl + go);
        }
        CP_COMMIT();
    };

    auto compute_stage = [&](int cur) {
        const uint32_t* Ah = smem_u + cur*STAGE;
        const uint32_t* Al = Ah + SZA;
        const uint32_t* Bh = Al + SZA;
        const uint32_t* Bl = Bh + SZB;
        #pragma unroll
        for (int ks = 0; ks < BK; ks += 16) {
            const int kp = ks >> 1;
            uint32_t ah[MT][4], al[MT][4], bh[NT][2], bl[NT][2];
            #pragma unroll
            for (int i = 0; i < MT; i++) {
                int mr = wm*WM + i*16 + g;
                ah[i][0] = Ah[mr*SP     + kp + c];   al[i][0] = Al[mr*SP     + kp + c];
                ah[i][1] = Ah[(mr+8)*SP + kp + c];   al[i][1] = Al[(mr+8)*SP + kp + c];
                ah[i][2] = Ah[mr*SP     + kp + c+4]; al[i][2] = Al[mr*SP     + kp + c+4];
                ah[i][3] = Ah[(mr+8)*SP + kp + c+4]; al[i][3] = Al[(mr+8)*SP + kp + c+4];
            }
            #pragma unroll
            for (int j = 0; j < NT; j++) {
                int nr = wn*WN + j*8 + g;
                bh[j][0] = Bh[nr*SP + kp + c];   bl[j][0] = Bl[nr*SP + kp + c];
                bh[j][1] = Bh[nr*SP + kp + c+4]; bl[j][1] = Bl[nr*SP + kp + c+4];
            }
            #pragma unroll
            for (int i = 0; i < MT; i++)
                #pragma unroll
                for (int j = 0; j < NT; j++)
                    mma_bf16(acc[i][j], ah[i], bh[j]);
            #pragma unroll
            for (int i = 0; i < MT; i++)
                #pragma unroll
                for (int j = 0; j < NT; j++)
                    mma_bf16(acc[i][j], ah[i], bl[j]);
            #pragma unroll
            for (int i = 0; i < MT; i++)
                #pragma unroll
                for (int j = 0; j < NT; j++)
                    mma_bf16(acc[i][j], al[i], bh[j]);
        }
    };

    cp_tile(0, 0);
    CP_WAIT0();
    __syncthreads();

    for (int t = 0; t < nk; t++) {
        const int cur = t & 1;
        if (t + 1 < nk) cp_tile((t+1)*BK, cur ^ 1);
        compute_stage(cur);
        if (t + 1 < nk) CP_WAIT0();
        __syncthreads();
    }

    // ---------------- epilogues ----------------
    if (EPI == EPI_QKV) {
        if (n0 < 2*D_) {
            const bool isq = (n0 < D_);
            #pragma unroll
            for (int i = 0; i < MT; i++) {
                #pragma unroll
                for (int jj = 0; jj < NT/2; jj++) {
                    #pragma unroll
                    for (int rr = 0; rr < 2; rr++) {
                        int m = m0 + wm*WM + i*16 + g + rr*8;
                        int s = m & (S_-1);
                        #pragma unroll
                        for (int t2 = 0; t2 < 2; t2++) {
                            int n = n0 + jj*8 + 2*c + t2;
                            float a  = acc[i][jj]  [rr*2+t2] + bias[n];
                            float bb = acc[i][jj+4][rr*2+t2] + bias[n+32];
                            int d = n & 63;
                            float co = g_cos[s*32 + d];
                            float si = g_sin[s*32 + d];
                            float r0 = a*co - bb*si;
                            float r1 = bb*co + a*si;
                            int col = isq ? (n & (D_-1)) : (n - D_);
                            size_t o = (size_t)m*D_ + col;
                            if (isq) {
                                split1(r0, s_q_h[o],    s_q_l[o]);
                                split1(r1, s_q_h[o+32], s_q_l[o+32]);
                            } else {
                                split1(r0, s_k_h[o],    s_k_l[o]);
                                split1(r1, s_k_h[o+32], s_k_l[o+32]);
                            }
                        }
                    }
                }
            }
        } else {
            #pragma unroll
            for (int i = 0; i < MT; i++) {
                #pragma unroll
                for (int j = 0; j < NT; j++) {
                    int n = n0 + wn*WN + j*8 + 2*c;
                    #pragma unroll
                    for (int rr = 0; rr < 2; rr++) {
                        int m = m0 + wm*WM + i*16 + g + rr*8;
                        float v0 = acc[i][j][rr*2]   + bias[n];
                        float v1 = acc[i][j][rr*2+1] + bias[n+1];
                        int dg = n - 2*D_;
                        int hh = dg >> 6, dd = dg & 63;
                        int b  = m >> 10, s = m & 1023;
                        size_t o0 = (((size_t)b*H_ + hh)*DH_ + dd)*S_ + s;
                        split1(v0, Oh[o0],    Ol[o0]);
                        split1(v1, Oh[o0+S_], Ol[o0+S_]);
                    }
                }
            }
        }
        return;
    }

    #pragma unroll
    for (int i = 0; i < MT; i++) {
        #pragma unroll
        for (int j = 0; j < NT; j++) {
            int n = n0 + wn*WN + j*8 + 2*c;
            #pragma unroll
            for (int rr = 0; rr < 2; rr++) {
                int m = m0 + wm*WM + i*16 + g + rr*8;
                float v0 = acc[i][j][rr*2 + 0];
                float v1 = acc[i][j][rr*2 + 1];
                if (EPI == EPI_SWIGLU) {
                    float sw = v0 / (1.f + expf(-v0)) * v1;
                    size_t oo = (size_t)m*(ldc >> 1) + (n >> 1);
                    split1(sw, Oh[oo], Ol[oo]);
                    continue;
                }
                size_t off = (size_t)m*ldc + n;
                if (EPI == EPI_BIAS_RES_AT) {
                    if (SPLITK == 1 || blockIdx.z == 0) { v0 += bias[n]; v1 += bias[n+1]; }
                    atomicAdd(C + off,     v0);
                    atomicAdd(C + off + 1, v1);
                } else if (EPI == EPI_RES_AT) {
                    atomicAdd(C + off,     v0);
                    atomicAdd(C + off + 1, v1);
                } else if (EPI == EPI_NONE) {
                    *(float2*)(C + off) = make_float2(v0, v1);
                }
            }
        }
    }
}

// ================== flash attention ==================
#define FA_SP 36
#define FA_TW (64*FA_SP)
#define FA_SMEM ((2*FA_TW + 2*4*FA_TW)*4)

__global__ __launch_bounds__(128, 2)
void flash_attn_kernel(float scale)
{
    extern __shared__ uint32_t sm[];
    const int tid  = threadIdx.x;
    const int warp = tid >> 5;
    const int lane = tid & 31;
    const int g = lane >> 2;
    const int c = lane & 3;
    const int mb = gridDim.x - 1 - blockIdx.x;   // LPT: longest blocks first
    const int bh = blockIdx.y;
    const int b  = bh >> 4;
    const int hh = bh & 15;
    const int m0 = mb * 64;

    const uint32_t smb = (uint32_t)__cvta_generic_to_shared(sm);
    uint32_t* sQh = sm;
    uint32_t* sQl = sm + FA_TW;

    const size_t vbase = (size_t)bh * DH_ * S_;

    #pragma unroll
    for (int i = 0; i < 4; i++) {
        int f = tid + i*128;
        int r = f >> 3, c8 = f & 7;
        size_t go = ((size_t)(b*S_ + m0 + r))*D_ + hh*64 + c8*8;
        uint32_t so = (uint32_t)(r*FA_SP + c8*4)*4;
        CP_ASYNC16(smb + so,             s_q_h + go);
        CP_ASYNC16(smb + FA_TW*4 + so,   s_q_l + go);
    }

    auto cp_kv = [&](int kb, int s) {
        uint32_t kvb = smb + (2*FA_TW + s*4*FA_TW)*4;
        #pragma unroll
        for (int i = 0; i < 4; i++) {
            int f = tid + i*128;
            int r = f >> 3, c8 = f & 7;
            uint32_t so = (uint32_t)(r*FA_SP + c8*4)*4;
            size_t gok = ((size_t)(b*S_ + kb*64 + r))*D_ + hh*64 + c8*8;
            CP_ASYNC16(kvb + so,             s_k_h + gok);
            CP_ASYNC16(kvb + FA_TW*4 + so,   s_k_l + gok);
            size_t gov = vbase + (size_t)r*S_ + kb*64 + c8*8;
            CP_ASYNC16(kvb + 2*FA_TW*4 + so, s_vt_h + gov);
            CP_ASYNC16(kvb + 3*FA_TW*4 + so, s_vt_l + gov);
        }
        CP_COMMIT();
    };

    cp_kv(0, 0);
    CP_WAIT0();
    __syncthreads();

    float m_r[2] = {-INFINITY, -INFINITY};
    float l_r[2] = {0.f, 0.f};
    float Oa[8][4];
    #pragma unroll
    for (int j = 0; j < 8; j++)
        #pragma unroll
        for (int r = 0; r < 4; r++) Oa[j][r] = 0.f;

    const int mr = warp*16 + g;

    for (int kb = 0; kb <= mb; kb++) {
        const int cur = kb & 1;
        if (kb < mb) cp_kv(kb+1, cur ^ 1);

        float Sa[8][4];
        #pragma unroll
        for (int j = 0; j < 8; j++)
            #pragma unroll
            for (int r = 0; r < 4; r++) Sa[j][r] = 0.f;

        {
            const uint32_t* Bh = sm + 2*FA_TW + cur*4*FA_TW;
            const uint32_t* Bl = Bh + FA_TW;
            #pragma unroll
            for (int ks = 0; ks < 64; ks += 16) {
                const int kp = ks >> 1;
                uint32_t ah[4], al[4], bh[8][2], bl[8][2];
                ah[0] = sQh[mr*FA_SP     + kp + c];   al[0] = sQl[mr*FA_SP     + kp + c];
                ah[1] = sQh[(mr+8)*FA_SP + kp + c];   al[1] = sQl[(mr+8)*FA_SP + kp + c];
                ah[2] = sQh[mr*FA_SP     + kp + c+4]; al[2] = sQl[mr*FA_SP     + kp + c+4];
                ah[3] = sQh[(mr+8)*FA_SP + kp + c+4]; al[3] = sQl[(mr+8)*FA_SP + kp + c+4];
                #pragma unroll
                for (int j = 0; j < 8; j++) {
                    int nr = j*8 + g;
                    bh[j][0] = Bh[nr*FA_SP + kp + c];   bl[j][0] = Bl[nr*FA_SP + kp + c];
                    bh[j][1] = Bh[nr*FA_SP + kp + c+4]; bl[j][1] = Bl[nr*FA_SP + kp + c+4];
                }
                #pragma unroll
                for (int j = 0; j < 8; j++) mma_bf16(Sa[j], ah, bh[j]);
                #pragma unroll
                for (int j = 0; j < 8; j++) mma_bf16(Sa[j], ah, bl[j]);
                #pragma unroll
                for (int j = 0; j < 8; j++) mma_bf16(Sa[j], al, bh[j]);
            }
        }

        #pragma unroll
        for (int j = 0; j < 8; j++)
            #pragma unroll
            for (int r = 0; r < 4; r++) Sa[j][r] *= scale;
        if (kb == mb) {
            #pragma unroll
            for (int j = 0; j < 8; j++) {
                int col = kb*64 + j*8 + 2*c;
                #pragma unroll
                for (int rr = 0; rr < 2; rr++) {
                    int row = m0 + mr + rr*8;
                    if (col     > row) Sa[j][rr*2]   = -INFINITY;
                    if (col + 1 > row) Sa[j][rr*2+1] = -INFINITY;
                }
            }
        }

        #pragma unroll
        for (int rr = 0; rr < 2; rr++) {
            float mx = -INFINITY;
            #pragma unroll
            for (int j = 0; j < 8; j++)
                mx = fmaxf(mx, fmaxf(Sa[j][rr*2], Sa[j][rr*2+1]));
            mx = fmaxf(mx, __shfl_xor_sync(0xffffffffu, mx, 1));
            mx = fmaxf(mx, __shfl_xor_sync(0xffffffffu, mx, 2));
            float mnew  = fmaxf(m_r[rr], mx);
            float alpha = expf(m_r[rr] - mnew);
            float sum = 0.f;
            #pragma unroll
            for (int j = 0; j < 8; j++) {
                float p0 = expf(Sa[j][rr*2]   - mnew);
                float p1 = expf(Sa[j][rr*2+1] - mnew);
                Sa[j][rr*2] = p0; Sa[j][rr*2+1] = p1;
                sum += p0 + p1;
            }
            sum += __shfl_xor_sync(0xffffffffu, sum, 1);
            sum += __shfl_xor_sync(0xffffffffu, sum, 2);
            l_r[rr] = l_r[rr]*alpha + sum;
            m_r[rr] = mnew;
            #pragma unroll
            for (int j = 0; j < 8; j++) {
                Oa[j][rr*2]   *= alpha;
                Oa[j][rr*2+1] *= alpha;
            }
        }

        {
            const uint32_t* Vh = sm + 2*FA_TW + cur*4*FA_TW + 2*FA_TW;
            const uint32_t* Vl = Vh + FA_TW;
            #pragma unroll
            for (int ks = 0; ks < 64; ks += 16) {
                const int j0 = ks >> 3;
                const int kp = ks >> 1;
                uint32_t ph[4], pl[4];
                splitpack2(Sa[j0][0],   Sa[j0][1],   ph[0], pl[0]);
                splitpack2(Sa[j0][2],   Sa[j0][3],   ph[1], pl[1]);
                splitpack2(Sa[j0+1][0], Sa[j0+1][1], ph[2], pl[2]);
                splitpack2(Sa[j0+1][2], Sa[j0+1][3], ph[3], pl[3]);
                uint32_t bh[8][2], bl[8][2];
                #pragma unroll
                for (int j = 0; j < 8; j++) {
                    int nr = j*8 + g;
                    bh[j][0] = Vh[nr*FA_SP + kp + c];   bl[j][0] = Vl[nr*FA_SP + kp + c];
                    bh[j][1] = Vh[nr*FA_SP + kp + c+4]; bl[j][1] = Vl[nr*FA_SP + kp + c+4];
                }
                #pragma unroll
                for (int j = 0; j < 8; j++) mma_bf16(Oa[j], ph, bh[j]);
                #pragma unroll
                for (int j = 0; j < 8; j++) mma_bf16(Oa[j], ph, bl[j]);
                #pragma unroll
                for (int j = 0; j < 8; j++) mma_bf16(Oa[j], pl, bh[j]);
            }
        }

        if (kb < mb) CP_WAIT0();
        __syncthreads();
    }

    float inv0 = 1.f / l_r[0];
    float inv1 = 1.f / l_r[1];
    #pragma unroll
    for (int j = 0; j < 8; j++) {
        int d = j*8 + 2*c;
        size_t t0 = (size_t)(b*S_ + m0 + mr)*D_ + hh*64 + d;
        split_store2(s_y_h, s_y_l, t0,          Oa[j][0]*inv0, Oa[j][1]*inv0);
        split_store2(s_y_h, s_y_l, t0 + 8*D_,   Oa[j][2]*inv1, Oa[j][3]*inv1);
    }
}

// ---------------- host ----------------
template<int BM, int BN, int BK>
constexpr int smem_bytes() {
    return 2 * (2*BM*(BK/2+4) + 2*BN*(BK/2+4)) * 4;
}

extern "C" void kernel_launch(void* const* d_in, const int* in_sizes, int n_in,
                              void* d_out, int out_size) {
    const int*   x      = (const int*)  d_in[0];
    const float* emb    = (const float*)d_in[1];
    const float* wq     = (const float*)d_in[2];
    const float* bq     = (const float*)d_in[3];
    const float* wk     = (const float*)d_in[4];
    const float* bk     = (const float*)d_in[5];
    const float* wv     = (const float*)d_in[6];
    const float* bv     = (const float*)d_in[7];
    const float* wo     = (const float*)d_in[8];
    const float* bo     = (const float*)d_in[9];
    const float* w_gate = (const float*)d_in[10];
    const float* w_up   = (const float*)d_in[11];
    const float* w_down = (const float*)d_in[12];
    const float* ln1    = (const float*)d_in[13];
    const float* ln2    = (const float*)d_in[14];
    const float* norm_w = (const float*)d_in[15];
    float* out = (float*)d_out;

    float *h, *bqkv;
    cudaGetSymbolAddress((void**)&h,    g_h);
    cudaGetSymbolAddress((void**)&bqkv, g_bqkv);

    bf16 *wqkvh,*wqkvl,*woh,*wol,*wguh,*wgul,*wdh,*wdl,*embh,*embl;
    bf16 *hnh,*hnl,*vth,*vtl,*yh,*yl,*gah,*gal;
    cudaGetSymbolAddress((void**)&wqkvh, s_wqkv_h); cudaGetSymbolAddress((void**)&wqkvl, s_wqkv_l);
    cudaGetSymbolAddress((void**)&woh, s_wo_h);  cudaGetSymbolAddress((void**)&wol, s_wo_l);
    cudaGetSymbolAddress((void**)&wguh, s_wgu_h); cudaGetSymbolAddress((void**)&wgul, s_wgu_l);
    cudaGetSymbolAddress((void**)&wdh, s_wd_h);  cudaGetSymbolAddress((void**)&wdl, s_wd_l);
    cudaGetSymbolAddress((void**)&embh, s_emb_h); cudaGetSymbolAddress((void**)&embl, s_emb_l);
    cudaGetSymbolAddress((void**)&hnh, s_hn_h);  cudaGetSymbolAddress((void**)&hnl, s_hn_l);
    cudaGetSymbolAddress((void**)&vth, s_vt_h);  cudaGetSymbolAddress((void**)&vtl, s_vt_l);
    cudaGetSymbolAddress((void**)&yh,  s_y_h);   cudaGetSymbolAddress((void**)&yl,  s_y_l);
    cudaGetSymbolAddress((void**)&gah, s_ga_h);  cudaGetSymbolAddress((void**)&gal, s_ga_l);

    constexpr int SM_S = smem_bytes<128,128,32>();   // 81920
    constexpr int SM_P = smem_bytes<128,64,32>();    // 61440
    constexpr int SM_L = smem_bytes<256,128,32>();   // 122880

    cudaFuncSetAttribute(gemm_tc<128,64,32,32,64,EPI_QKV,3,1>,         cudaFuncAttributeMaxDynamicSharedMemorySize, SM_P);
    cudaFuncSetAttribute(gemm_tc<128,64,32,64,32,EPI_BIAS_RES_AT,3,2>, cudaFuncAttributeMaxDynamicSharedMemorySize, SM_P);
    cudaFuncSetAttribute(gemm_tc<128,128,32,64,64,EPI_SWIGLU,2,1>,     cudaFuncAttributeMaxDynamicSharedMemorySize, SM_S);
    cudaFuncSetAttribute(gemm_tc<128,64,32,64,32,EPI_RES_AT,3,4>,      cudaFuncAttributeMaxDynamicSharedMemorySize, SM_P);
    cudaFuncSetAttribute(gemm_tc<256,128,32,64,64,EPI_NONE,1,1>,       cudaFuncAttributeMaxDynamicSharedMemorySize, SM_L);
    cudaFuncSetAttribute(flash_attn_kernel,                            cudaFuncAttributeMaxDynamicSharedMemorySize, FA_SMEM);

    // ---- prep ----
    auto split_launch = [](const float* src, bf16* dh, bf16* dl, size_t n) {
        int n4 = (int)(n / 4);
        split_kernel<<<(n4 + 255)/256, 256>>>(src, dh, dl, n4);
    };
    int nw4 = L_*D_*D_/4;
    split_pack_kernel<<<(nw4+255)/256, 256>>>(wq, wqkvh, wqkvl, 0);
    split_pack_kernel<<<(nw4+255)/256, 256>>>(wk, wqkvh, wqkvl, D_);
    split_pack_kernel<<<(nw4+255)/256, 256>>>(wv, wqkvh, wqkvl, 2*D_);
    pack_bias_kernel<<<(L_*3*D_+255)/256, 256>>>(bq, bk, bv, bqkv);
    split_launch(wo, woh, wol, (size_t)L_*D_*D_);
    int ngu4 = L_*DI_*D_/4;
    split_pack_gu_kernel<<<(ngu4+255)/256, 256>>>(w_gate, w_up, wguh, wgul);
    split_launch(w_down, wdh, wdl, (size_t)L_*D_*DI_);
    split_launch(emb, embh, embl, (size_t)V_*D_);

    embed_kernel<<<T_*D_/4/256, 256>>>(x, emb, h);
    rope_cache_kernel<<<(S_*32 + 255)/256, 256>>>();

    const dim3 gqkv(3*D_/64, T_/128, 1);
    const dim3 gpz2(D_/64,  T_/128, 2);      // wo: split-K x2
    const dim3 gpz4(D_/64,  T_/128, 4);      // down: split-K x4
    const dim3 ggu(2*DI_/128, T_/128, 1);
    const dim3 gfa(S_/64, B_*H_, 1);

    for (int l = 0; l < L_; l++) {
        rmsnorm_kernel<<<T_, 256>>>(h, ln1 + (size_t)l*D_, hnh, hnl);

        gemm_tc<128,64,32,32,64,EPI_QKV,3,1><<<gqkv,128,SM_P>>>(
            hnh, hnl, wqkvh + (size_t)l*3*D_*D_, wqkvl + (size_t)l*3*D_*D_,
            nullptr, vth, vtl, bqkv + (size_t)l*3*D_,
            T_, 3*D_, D_, D_, D_, 0);

        flash_attn_kernel<<<gfa, 128, FA_SMEM>>>(0.125f);

        gemm_tc<128,64,32,64,32,EPI_BIAS_RES_AT,3,2><<<gpz2,128,SM_P>>>(
            yh, yl, woh + (size_t)l*D_*D_, wol + (size_t)l*D_*D_,
            h, nullptr, nullptr, bo + (size_t)l*D_,
            T_, D_, D_, D_, D_, D_);

        rmsnorm_kernel<<<T_, 256>>>(h, ln2 + (size_t)l*D_, hnh, hnl);

        gemm_tc<128,128,32,64,64,EPI_SWIGLU,2,1><<<ggu,128,SM_S>>>(
            hnh, hnl, wguh + (size_t)l*2*DI_*D_, wgul + (size_t)l*2*DI_*D_,
            nullptr, gah, gal, nullptr,
            T_, 2*DI_, D_, D_, D_, 2*DI_);

        gemm_tc<128,64,32,64,32,EPI_RES_AT,3,4><<<gpz4,128,SM_P>>>(
            gah, gal, wdh + (size_t)l*D_*DI_, wdl + (size_t)l*D_*DI_,
            h, nullptr, nullptr, nullptr,
            T_, D_, DI_, DI_, DI_, D_);
    }

    rmsnorm_kernel<<<T_, 256>>>(h, norm_w, hnh, hnl);

    // logits: BM=256 tiles halve B (embedding) traffic — emb exceeds L2.
    const dim3 gl(V_/128, T_/256, 1);
    gemm_tc<256,128,32,64,64,EPI_NONE,1,1><<<gl,256,SM_L>>>(
        hnh, hnl, embh, embl, out, nullptr, nullptr, nullptr,
        T_, V_, D_, D_, D_, V_);
}